// round 3
// baseline (speedup 1.0000x reference)
#include <cuda_runtime.h>
#include <math.h>

// ---------------------------------------------------------------------------
// Problem constants
// ---------------------------------------------------------------------------
namespace {
constexpr int B_ = 128, L_ = 128, D_ = 6, FD_ = 256;
constexpr int IN_ATOM_ = 39, IN_BOND_ = 10, NBONDS_ = 256;
constexpr int RADIUS_ = 3, TASKS_ = 4, T_ = 2;
constexpr int BL_ = B_ * L_;        // 16384
constexpr int BLD_ = BL_ * D_;      // 98304
constexpr float NEG_ = -9e8f;
}

// ---------------------------------------------------------------------------
// Scratch buffers (device globals; no allocations allowed)
// ---------------------------------------------------------------------------
__device__ float g_atomfeat[BL_ * FD_];
__device__ float g_nbrfeat [BLD_ * FD_];
__device__ float g_h       [BL_ * FD_];
__device__ float g_act     [BL_ * FD_];
__device__ float g_wf      [BL_ * FD_];
__device__ float g_ctx     [BL_ * FD_];
__device__ float g_actT    [BL_ * FD_];
__device__ float g_gi      [BL_ * 3 * FD_];
__device__ float g_gh      [BL_ * 3 * FD_];
__device__ float g_nbrdot0 [BLD_];
__device__ float g_sd      [BL_];
__device__ float g_nd      [BL_];
__device__ float g_w       [BLD_];
__device__ float g_wsum    [BL_];
__device__ float g_actdot  [TASKS_ * BL_];
__device__ float g_molfeat [B_ * FD_];
__device__ float g_actmol  [B_ * FD_];
__device__ float g_molw    [BL_];
__device__ float g_molctx  [B_ * FD_];
__device__ float g_mgi     [B_ * 3 * FD_];
__device__ float g_mgh     [B_ * 3 * FD_];

__device__ __forceinline__ float lrelu_(float x) { return x > 0.f ? x : 0.01f * x; }
__device__ __forceinline__ float elu_(float x)   { return x > 0.f ? x : expm1f(x); }
__device__ __forceinline__ float sigm_(float x)  { return 1.f / (1.f + expf(-x)); }

// ---------------------------------------------------------------------------
// Generic GEMM: C[M,N] = A[M,K] @ W[N,K]^T  (row-major A, row-major W)
// MODE 0: C = acc + bias[n]
// MODE 1: C = lrelu(acc + bias[n])
// MODE 2: C = elu(acc + rowscale[m] * bias[n])
// Requires M%64==0, N%64==0, K%16==0.
// ---------------------------------------------------------------------------
template <int MODE>
__global__ __launch_bounds__(256)
void gemm64(const float* __restrict__ A, const float* __restrict__ W,
            const float* __restrict__ bias, const float* __restrict__ rs,
            float* __restrict__ C, int M, int N, int K)
{
    __shared__ float As[16][64];
    __shared__ float Ws[16][64];
    const int tid = threadIdx.x;
    const int tx = tid & 15, ty = tid >> 4;
    const int bm = blockIdx.y * 64, bn = blockIdx.x * 64;
    const int lr = tid >> 2;          // 0..63
    const int lk = (tid & 3) << 2;    // 0,4,8,12
    const float* Ap = A + (size_t)(bm + lr) * K + lk;
    const float* Wp = W + (size_t)(bn + lr) * K + lk;
    float acc[4][4] = {};
    for (int kt = 0; kt < K; kt += 16) {
        float4 av = *reinterpret_cast<const float4*>(Ap + kt);
        float4 wv = *reinterpret_cast<const float4*>(Wp + kt);
        As[lk + 0][lr] = av.x; As[lk + 1][lr] = av.y; As[lk + 2][lr] = av.z; As[lk + 3][lr] = av.w;
        Ws[lk + 0][lr] = wv.x; Ws[lk + 1][lr] = wv.y; Ws[lk + 2][lr] = wv.z; Ws[lk + 3][lr] = wv.w;
        __syncthreads();
#pragma unroll
        for (int k = 0; k < 16; k++) {
            float4 a = *reinterpret_cast<const float4*>(&As[k][ty << 2]);
            float4 b = *reinterpret_cast<const float4*>(&Ws[k][tx << 2]);
            acc[0][0] += a.x * b.x; acc[0][1] += a.x * b.y; acc[0][2] += a.x * b.z; acc[0][3] += a.x * b.w;
            acc[1][0] += a.y * b.x; acc[1][1] += a.y * b.y; acc[1][2] += a.y * b.z; acc[1][3] += a.y * b.w;
            acc[2][0] += a.z * b.x; acc[2][1] += a.z * b.y; acc[2][2] += a.z * b.z; acc[2][3] += a.z * b.w;
            acc[3][0] += a.w * b.x; acc[3][1] += a.w * b.y; acc[3][2] += a.w * b.z; acc[3][3] += a.w * b.w;
        }
        __syncthreads();
    }
#pragma unroll
    for (int i = 0; i < 4; i++) {
        int m = bm + (ty << 2) + i;
        float rsv = (MODE == 2) ? rs[m] : 0.f;
#pragma unroll
        for (int j = 0; j < 4; j++) {
            int n = bn + (tx << 2) + j;
            float v = acc[i][j];
            if (MODE == 0)      { v += bias[n]; }
            else if (MODE == 1) { v += bias[n]; v = lrelu_(v); }
            else                { v += rsv * bias[n]; v = elu_(v); }
            C[(size_t)m * N + n] = v;
        }
    }
}

// ---------------------------------------------------------------------------
// atom_fc: C[BL,256] = lrelu(X[BL,39] @ W[256,39]^T + b)
// ---------------------------------------------------------------------------
__global__ __launch_bounds__(256)
void fp_atom_fc(const float* __restrict__ X, const float* __restrict__ W,
                const float* __restrict__ bias, float* __restrict__ C)
{
    __shared__ float sin_[16][IN_ATOM_];
    const int r0 = blockIdx.x * 16;
    for (int i = threadIdx.x; i < 16 * IN_ATOM_; i += 256)
        sin_[i / IN_ATOM_][i % IN_ATOM_] =
            X[(size_t)(r0 + i / IN_ATOM_) * IN_ATOM_ + i % IN_ATOM_];
    __syncthreads();
    const int f = threadIdx.x;
    float acc[16] = {};
    for (int k = 0; k < IN_ATOM_; k++) {
        float wv = __ldg(&W[f * IN_ATOM_ + k]);
#pragma unroll
        for (int r = 0; r < 16; r++) acc[r] += wv * sin_[r][k];
    }
    float bv = bias[f];
#pragma unroll
    for (int r = 0; r < 16; r++)
        C[(size_t)(r0 + r) * FD_ + f] = lrelu_(acc[r] + bv);
}

// ---------------------------------------------------------------------------
// neighbor_fc: gather concat(atom_list[idxA], bond_list[idxB]) then FC + lrelu
// C[BLD,256]
// ---------------------------------------------------------------------------
__global__ __launch_bounds__(256)
void fp_neighbor_fc(const float* __restrict__ atom_list, const float* __restrict__ bond_list,
                    const int* __restrict__ adeg, const int* __restrict__ bdeg,
                    const float* __restrict__ W, const float* __restrict__ bias,
                    float* __restrict__ C)
{
    constexpr int KIN = IN_ATOM_ + IN_BOND_;   // 49
    __shared__ float sin_[16][KIN];
    const int r0 = blockIdx.x * 16;
    for (int i = threadIdx.x; i < 16 * KIN; i += 256) {
        int r = i / KIN, k = i % KIN;
        int rid = r0 + r;
        int bb = rid / (L_ * D_);
        float v;
        if (k < IN_ATOM_) {
            int ia = adeg[rid];
            v = atom_list[((size_t)bb * L_ + ia) * IN_ATOM_ + k];
        } else {
            int ib = bdeg[rid];
            v = bond_list[((size_t)bb * NBONDS_ + ib) * IN_BOND_ + (k - IN_ATOM_)];
        }
        sin_[r][k] = v;
    }
    __syncthreads();
    const int f = threadIdx.x;
    float acc[16] = {};
    for (int k = 0; k < KIN; k++) {
        float wv = __ldg(&W[f * KIN + k]);
#pragma unroll
        for (int r = 0; r < 16; r++) acc[r] += wv * sin_[r][k];
    }
    float bv = bias[f];
#pragma unroll
    for (int r = 0; r < 16; r++)
        C[(size_t)(r0 + r) * FD_ + f] = lrelu_(acc[r] + bv);
}

// ---------------------------------------------------------------------------
// Warp-per-row dot products (K = 256)
// ---------------------------------------------------------------------------
__global__ void fp_rowdot(const float* __restrict__ X, const float* __restrict__ v,
                          float* __restrict__ y, int M)
{
    int warp = (blockIdx.x * blockDim.x + threadIdx.x) >> 5;
    int lane = threadIdx.x & 31;
    if (warp >= M) return;
    const float* x = X + (size_t)warp * FD_;
    float s = 0.f;
#pragma unroll
    for (int k = lane; k < FD_; k += 32) s += x[k] * v[k];
#pragma unroll
    for (int o = 16; o; o >>= 1) s += __shfl_down_sync(0xffffffffu, s, o);
    if (lane == 0) y[warp] = s;
}

__global__ void fp_rowdot2(const float* __restrict__ X, const float* __restrict__ v1,
                           const float* __restrict__ v2,
                           float* __restrict__ y1, float* __restrict__ y2, int M)
{
    int warp = (blockIdx.x * blockDim.x + threadIdx.x) >> 5;
    int lane = threadIdx.x & 31;
    if (warp >= M) return;
    const float* x = X + (size_t)warp * FD_;
    float s1 = 0.f, s2 = 0.f;
#pragma unroll
    for (int k = lane; k < FD_; k += 32) {
        float xv = x[k];
        s1 += xv * v1[k];
        s2 += xv * v2[k];
    }
#pragma unroll
    for (int o = 16; o; o >>= 1) {
        s1 += __shfl_down_sync(0xffffffffu, s1, o);
        s2 += __shfl_down_sync(0xffffffffu, s2, o);
    }
    if (lane == 0) { y1[warp] = s1; y2[warp] = s2; }
}

// 4 simultaneous dots against mol_align_w[i][0][256:512]
__global__ void fp_actdot4(const float* __restrict__ X, const float* __restrict__ maw,
                           float* __restrict__ y)
{
    int warp = (blockIdx.x * blockDim.x + threadIdx.x) >> 5;
    int lane = threadIdx.x & 31;
    if (warp >= BL_) return;
    const float* x = X + (size_t)warp * FD_;
    float s0 = 0.f, s1 = 0.f, s2 = 0.f, s3 = 0.f;
#pragma unroll
    for (int k = lane; k < FD_; k += 32) {
        float xv = x[k];
        s0 += xv * maw[0 * 512 + 256 + k];
        s1 += xv * maw[1 * 512 + 256 + k];
        s2 += xv * maw[2 * 512 + 256 + k];
        s3 += xv * maw[3 * 512 + 256 + k];
    }
#pragma unroll
    for (int o = 16; o; o >>= 1) {
        s0 += __shfl_down_sync(0xffffffffu, s0, o);
        s1 += __shfl_down_sync(0xffffffffu, s1, o);
        s2 += __shfl_down_sync(0xffffffffu, s2, o);
        s3 += __shfl_down_sync(0xffffffffu, s3, o);
    }
    if (lane == 0) {
        y[0 * BL_ + warp] = s0; y[1 * BL_ + warp] = s1;
        y[2 * BL_ + warp] = s2; y[3 * BL_ + warp] = s3;
    }
}

// ---------------------------------------------------------------------------
// Attention scores + softmax over D=6. FIRST: nd indexed per (m,d); else
// gathered per atom via adeg.
// ---------------------------------------------------------------------------
template <int FIRST>
__global__ void fp_score(const float* __restrict__ sd, const float* __restrict__ nd,
                         const int* __restrict__ adeg, const float* __restrict__ ab_ptr,
                         float* __restrict__ w, float* __restrict__ wsum)
{
    int m = blockIdx.x * blockDim.x + threadIdx.x;
    if (m >= BL_) return;
    int b = m / L_;
    float ab = ab_ptr[0];
    float sdv = sd[m];
    float sc[D_], msk[D_];
    float mx = -3.4e38f;
#pragma unroll
    for (int d = 0; d < D_; d++) {
        int idx = adeg[m * D_ + d];
        float ndv = FIRST ? nd[m * D_ + d] : nd[b * L_ + idx];
        float s = lrelu_(sdv + ndv + ab);
        bool pad = (idx == L_ - 1);
        if (pad) s += NEG_;
        msk[d] = pad ? 0.f : 1.f;
        sc[d] = s;
        mx = fmaxf(mx, s);
    }
    float sum = 0.f;
#pragma unroll
    for (int d = 0; d < D_; d++) { float e = expf(sc[d] - mx); sum += e; sc[d] = e; }
    float inv = 1.f / sum, ws = 0.f;
#pragma unroll
    for (int d = 0; d < D_; d++) {
        float wv = sc[d] * inv * msk[d];
        w[m * D_ + d] = wv;
        ws += wv;
    }
    wsum[m] = ws;
}

// ---------------------------------------------------------------------------
// Weighted neighbor-feature sum: wf[m,f] = sum_d w[m,d] * nbr(m,d)[f]
// FIRST: nbr = g_nbrfeat rows; else nbr = g_act gathered via adeg.
// ---------------------------------------------------------------------------
template <int FIRST>
__global__ __launch_bounds__(256)
void fp_wf(const float* __restrict__ w, const int* __restrict__ adeg,
           const float* __restrict__ src, float* __restrict__ wf)
{
    __shared__ float sw[2][D_];
    __shared__ int sidx[2][D_];
    const int m0 = blockIdx.x * 2;
    if (threadIdx.x < 2 * D_) {
        int r = threadIdx.x / D_, d = threadIdx.x % D_;
        sw[r][d] = w[(m0 + r) * D_ + d];
        sidx[r][d] = adeg[(m0 + r) * D_ + d];
    }
    __syncthreads();
    const int f = threadIdx.x;
#pragma unroll
    for (int r = 0; r < 2; r++) {
        int m = m0 + r;
        int b = m / L_;
        float acc = 0.f;
#pragma unroll
        for (int d = 0; d < D_; d++) {
            float xv = FIRST ? src[((size_t)m * D_ + d) * FD_ + f]
                             : src[(size_t)(b * L_ + sidx[r][d]) * FD_ + f];
            acc += sw[r][d] * xv;
        }
        wf[(size_t)m * FD_ + f] = acc;
    }
}

// ---------------------------------------------------------------------------
// GRU gate fuse: h' = (1-z)*n + z*h ; also writes relu(h') to act (and out)
// ---------------------------------------------------------------------------
__global__ void fp_gru_gate(const float* __restrict__ gi, const float* __restrict__ gh,
                            const float* __restrict__ hin, float* __restrict__ hout,
                            float* __restrict__ act, float* __restrict__ out, int M)
{
    int g = blockIdx.x * blockDim.x + threadIdx.x;
    if (g >= M * FD_) return;
    int m = g / FD_, f = g - m * FD_;
    const float* gim = gi + (size_t)m * 3 * FD_;
    const float* ghm = gh + (size_t)m * 3 * FD_;
    float r = sigm_(gim[f] + ghm[f]);
    float z = sigm_(gim[FD_ + f] + ghm[FD_ + f]);
    float n = tanhf(gim[2 * FD_ + f] + r * ghm[2 * FD_ + f]);
    float h = (1.f - z) * n + z * hin[g];
    hout[g] = h;
    float a = fmaxf(h, 0.f);
    if (act) act[g] = a;
    if (out) out[g] = a;
}

// ---------------------------------------------------------------------------
// Molecule-level kernels
// ---------------------------------------------------------------------------
__global__ void fp_molfeat(const float* __restrict__ act, const float* __restrict__ amask,
                           float* __restrict__ mf, float* __restrict__ am)
{
    int b = blockIdx.x, f = threadIdx.x;
    float acc = 0.f;
    for (int l = 0; l < L_; l++)
        acc += act[((size_t)b * L_ + l) * FD_ + f] * amask[b * L_ + l];
    mf[b * FD_ + f] = acc;
    am[b * FD_ + f] = fmaxf(acc, 0.f);
}

__global__ __launch_bounds__(128)
void fp_molscore(const float* __restrict__ actmol, const float* __restrict__ maw,
                 const float* __restrict__ mab, const float* __restrict__ actdot,
                 const float* __restrict__ amask, float* __restrict__ wout, int task)
{
    __shared__ float red[128];
    int b = blockIdx.x, t = threadIdx.x;
    const float* ms = maw + task * 2 * FD_;   // self half [0:256)
    float p = actmol[b * FD_ + t] * ms[t] + actmol[b * FD_ + 128 + t] * ms[128 + t];
    red[t] = p; __syncthreads();
    for (int st = 64; st; st >>= 1) { if (t < st) red[t] += red[t + st]; __syncthreads(); }
    float sdv = red[0]; __syncthreads();
    float amv = amask[b * L_ + t];
    float s = lrelu_(sdv + actdot[task * BL_ + b * L_ + t] + mab[task]);
    if (amv == 0.f) s += NEG_;
    red[t] = s; __syncthreads();
    for (int st = 64; st; st >>= 1) { if (t < st) red[t] = fmaxf(red[t], red[t + st]); __syncthreads(); }
    float mx = red[0]; __syncthreads();
    float e = expf(s - mx);
    red[t] = e; __syncthreads();
    for (int st = 64; st; st >>= 1) { if (t < st) red[t] += red[t + st]; __syncthreads(); }
    float sum = red[0];
    wout[b * L_ + t] = e / sum * amv;
}

__global__ void fp_molctx(const float* __restrict__ w, const float* __restrict__ actT,
                          float* __restrict__ ctx)
{
    int b = blockIdx.x, f = threadIdx.x;
    float acc = 0.f;
    for (int l = 0; l < L_; l++)
        acc += w[b * L_ + l] * actT[((size_t)b * L_ + l) * FD_ + f];
    ctx[b * FD_ + f] = elu_(acc);
}

// ---------------------------------------------------------------------------
// Host launch sequence
// ---------------------------------------------------------------------------
extern "C" void kernel_launch(void* const* d_in, const int* in_sizes, int n_in,
                              void* d_out, int out_size)
{
    const float* atom_list = (const float*)d_in[0];
    const float* bond_list = (const float*)d_in[1];
    const int*   adeg      = (const int*)d_in[2];
    const int*   bdeg      = (const int*)d_in[3];
    const float* amask     = (const float*)d_in[4];
    const float* atom_fc_w = (const float*)d_in[5];
    const float* atom_fc_b = (const float*)d_in[6];
    const float* nbr_fc_w  = (const float*)d_in[7];
    const float* nbr_fc_b  = (const float*)d_in[8];
    const float* align_w   = (const float*)d_in[9];
    const float* align_b   = (const float*)d_in[10];
    const float* attend_w  = (const float*)d_in[11];
    const float* attend_b  = (const float*)d_in[12];
    const float* gru_wih   = (const float*)d_in[13];
    const float* gru_whh   = (const float*)d_in[14];
    const float* gru_bih   = (const float*)d_in[15];
    const float* gru_bhh   = (const float*)d_in[16];
    const float* mgru_wih  = (const float*)d_in[17];
    const float* mgru_whh  = (const float*)d_in[18];
    const float* mgru_bih  = (const float*)d_in[19];
    const float* mgru_bhh  = (const float*)d_in[20];
    const float* mal_w     = (const float*)d_in[21];
    const float* mal_b     = (const float*)d_in[22];
    const float* mat_w     = (const float*)d_in[23];
    const float* mat_b     = (const float*)d_in[24];
    float* out = (float*)d_out;

    float *p_atomfeat, *p_nbrfeat, *p_h, *p_act, *p_wf, *p_ctx, *p_actT,
          *p_gi, *p_gh, *p_nbrdot0, *p_sd, *p_nd, *p_w, *p_wsum, *p_actdot,
          *p_molfeat, *p_actmol, *p_molw, *p_molctx, *p_mgi, *p_mgh;
    cudaGetSymbolAddress((void**)&p_atomfeat, g_atomfeat);
    cudaGetSymbolAddress((void**)&p_nbrfeat,  g_nbrfeat);
    cudaGetSymbolAddress((void**)&p_h,        g_h);
    cudaGetSymbolAddress((void**)&p_act,      g_act);
    cudaGetSymbolAddress((void**)&p_wf,       g_wf);
    cudaGetSymbolAddress((void**)&p_ctx,      g_ctx);
    cudaGetSymbolAddress((void**)&p_actT,     g_actT);
    cudaGetSymbolAddress((void**)&p_gi,       g_gi);
    cudaGetSymbolAddress((void**)&p_gh,       g_gh);
    cudaGetSymbolAddress((void**)&p_nbrdot0,  g_nbrdot0);
    cudaGetSymbolAddress((void**)&p_sd,       g_sd);
    cudaGetSymbolAddress((void**)&p_nd,       g_nd);
    cudaGetSymbolAddress((void**)&p_w,        g_w);
    cudaGetSymbolAddress((void**)&p_wsum,     g_wsum);
    cudaGetSymbolAddress((void**)&p_actdot,   g_actdot);
    cudaGetSymbolAddress((void**)&p_molfeat,  g_molfeat);
    cudaGetSymbolAddress((void**)&p_actmol,   g_actmol);
    cudaGetSymbolAddress((void**)&p_molw,     g_molw);
    cudaGetSymbolAddress((void**)&p_molctx,   g_molctx);
    cudaGetSymbolAddress((void**)&p_mgi,      g_mgi);
    cudaGetSymbolAddress((void**)&p_mgh,      g_mgh);

    const dim3 gctx(FD_ / 64, BL_ / 64);        // 16384 x 256 GEMM
    const dim3 ggru(3 * FD_ / 64, BL_ / 64);    // 16384 x 768 GEMM
    const dim3 gmol(3 * FD_ / 64, B_ / 64);     // 128 x 768 GEMM

    // --- atom & neighbor features ---
    fp_atom_fc<<<BL_ / 16, 256>>>(atom_list, atom_fc_w, atom_fc_b, p_atomfeat);
    fp_neighbor_fc<<<BLD_ / 16, 256>>>(atom_list, bond_list, adeg, bdeg,
                                       nbr_fc_w, nbr_fc_b, p_nbrfeat);

    // --- radius 0 ---
    fp_rowdot<<<BLD_ / 8, 256>>>(p_nbrfeat, align_w + 256, p_nbrdot0, BLD_);
    fp_rowdot<<<BL_ / 8, 256>>>(p_atomfeat, align_w, p_sd, BL_);
    fp_score<1><<<BL_ / 256, 256>>>(p_sd, p_nbrdot0, adeg, align_b, p_w, p_wsum);
    fp_wf<1><<<BL_ / 2, 256>>>(p_w, adeg, p_nbrfeat, p_wf);
    gemm64<2><<<gctx, 256>>>(p_wf, attend_w, attend_b, p_wsum, p_ctx, BL_, FD_, FD_);
    gemm64<0><<<ggru, 256>>>(p_ctx, gru_wih, gru_bih, nullptr, p_gi, BL_, 3 * FD_, FD_);
    gemm64<0><<<ggru, 256>>>(p_atomfeat, gru_whh, gru_bhh, nullptr, p_gh, BL_, 3 * FD_, FD_);
    fp_gru_gate<<<BL_ * FD_ / 256, 256>>>(p_gi, p_gh, p_atomfeat, p_h, p_act, nullptr, BL_);

    // --- radius 1..2 ---
    for (int r = 1; r < RADIUS_; r++) {
        fp_rowdot2<<<BL_ / 8, 256>>>(p_act, align_w + r * 512, align_w + r * 512 + 256,
                                     p_sd, p_nd, BL_);
        fp_score<0><<<BL_ / 256, 256>>>(p_sd, p_nd, adeg, align_b + r, p_w, p_wsum);
        fp_wf<0><<<BL_ / 2, 256>>>(p_w, adeg, p_act, p_wf);
        gemm64<2><<<gctx, 256>>>(p_wf, attend_w + (size_t)r * FD_ * FD_,
                                 attend_b + r * FD_, p_wsum, p_ctx, BL_, FD_, FD_);
        gemm64<0><<<ggru, 256>>>(p_ctx, gru_wih + (size_t)r * 3 * FD_ * FD_,
                                 gru_bih + r * 3 * FD_, nullptr, p_gi, BL_, 3 * FD_, FD_);
        gemm64<0><<<ggru, 256>>>(p_h, gru_whh + (size_t)r * 3 * FD_ * FD_,
                                 gru_bhh + r * 3 * FD_, nullptr, p_gh, BL_, 3 * FD_, FD_);
        fp_gru_gate<<<BL_ * FD_ / 256, 256>>>(p_gi, p_gh, p_h, p_h, p_act, nullptr, BL_);
    }

    // --- molecule phase ---
    fp_molfeat<<<B_, FD_>>>(p_act, amask, p_molfeat, p_actmol);
    gemm64<0><<<gctx, 256>>>(p_act, mat_w, mat_b, nullptr, p_actT, BL_, FD_, FD_);
    fp_actdot4<<<BL_ / 8, 256>>>(p_act, mal_w, p_actdot);

    for (int i = 0; i < TASKS_; i++) {
        for (int t = 0; t < T_; t++) {
            fp_molscore<<<B_, 128>>>(p_actmol, mal_w, mal_b, p_actdot, amask, p_molw, i);
            fp_molctx<<<B_, FD_>>>(p_molw, p_actT, p_molctx);
            gemm64<0><<<gmol, 256>>>(p_molctx, mgru_wih, mgru_bih, nullptr, p_mgi, B_, 3 * FD_, FD_);
            gemm64<0><<<gmol, 256>>>(p_molfeat, mgru_whh, mgru_bhh, nullptr, p_mgh, B_, 3 * FD_, FD_);
            fp_gru_gate<<<B_ * FD_ / 256, 256>>>(p_mgi, p_mgh, p_molfeat, p_molfeat, p_actmol,
                                                 (t == T_ - 1) ? out + (size_t)i * B_ * FD_
                                                               : nullptr,
                                                 B_);
        }
    }
}

// round 5
// speedup vs baseline: 2.0230x; 2.0230x over previous
#include <cuda_runtime.h>
#include <cuda_bf16.h>
#include <math.h>
#include <stdint.h>

// ---------------------------------------------------------------------------
// Problem constants
// ---------------------------------------------------------------------------
namespace {
constexpr int B_ = 128, L_ = 128, D_ = 6, FD_ = 256;
constexpr int IN_ATOM_ = 39, IN_BOND_ = 10, NBONDS_ = 256;
constexpr int RADIUS_ = 3, TASKS_ = 4, T_ = 2;
constexpr int BL_ = B_ * L_;        // 16384
constexpr int BLD_ = BL_ * D_;      // 98304
constexpr float NEG_ = -9e8f;
constexpr int GN_ = 3 * FD_;        // 768
}

// ---------------------------------------------------------------------------
// Scratch buffers (device globals; no allocations allowed)
// ---------------------------------------------------------------------------
__device__ float g_atomfeat[BL_ * FD_];
__device__ float g_nbrfeat [BLD_ * FD_];
__device__ float g_h       [BL_ * FD_];
__device__ float g_act     [BL_ * FD_];
__device__ float g_actT    [BL_ * FD_];
__device__ float g_gi      [BL_ * GN_];
__device__ float g_gh      [BL_ * GN_];
__device__ float g_nbrdot0 [BLD_];
__device__ float g_sd      [BL_];
__device__ float g_nd      [BL_];
__device__ float g_w       [BLD_];
__device__ float g_wsum    [BL_];
__device__ float g_actdot  [TASKS_ * BL_];
__device__ float g_molfeat [B_ * FD_];
__device__ float g_actmol  [B_ * FD_];
__device__ float g_mgi     [B_ * GN_];
__device__ float g_mgh     [B_ * GN_];

// bf16 hi/lo activation buffers (16B aligned for uint4 staging)
__device__ __align__(16) __nv_bfloat16 g_af_h [BL_ * FD_];
__device__ __align__(16) __nv_bfloat16 g_af_l [BL_ * FD_];
__device__ __align__(16) __nv_bfloat16 g_wf_h [BL_ * FD_];
__device__ __align__(16) __nv_bfloat16 g_wf_l [BL_ * FD_];
__device__ __align__(16) __nv_bfloat16 g_ctx_h[BL_ * FD_];
__device__ __align__(16) __nv_bfloat16 g_ctx_l[BL_ * FD_];
__device__ __align__(16) __nv_bfloat16 g_h_h  [BL_ * FD_];
__device__ __align__(16) __nv_bfloat16 g_h_l  [BL_ * FD_];
__device__ __align__(16) __nv_bfloat16 g_act_h[BL_ * FD_];
__device__ __align__(16) __nv_bfloat16 g_act_l[BL_ * FD_];
__device__ __align__(16) __nv_bfloat16 g_mctx_h[B_ * FD_];
__device__ __align__(16) __nv_bfloat16 g_mctx_l[B_ * FD_];
__device__ __align__(16) __nv_bfloat16 g_mf_h [B_ * FD_];
__device__ __align__(16) __nv_bfloat16 g_mf_l [B_ * FD_];
// bf16 hi/lo weights
__device__ __align__(16) __nv_bfloat16 g_watt_h[RADIUS_ * FD_ * FD_];
__device__ __align__(16) __nv_bfloat16 g_watt_l[RADIUS_ * FD_ * FD_];
__device__ __align__(16) __nv_bfloat16 g_wih_h [RADIUS_ * GN_ * FD_];
__device__ __align__(16) __nv_bfloat16 g_wih_l [RADIUS_ * GN_ * FD_];
__device__ __align__(16) __nv_bfloat16 g_whh_h [RADIUS_ * GN_ * FD_];
__device__ __align__(16) __nv_bfloat16 g_whh_l [RADIUS_ * GN_ * FD_];
__device__ __align__(16) __nv_bfloat16 g_mat_h [FD_ * FD_];
__device__ __align__(16) __nv_bfloat16 g_mat_l [FD_ * FD_];
__device__ __align__(16) __nv_bfloat16 g_mih_h [GN_ * FD_];
__device__ __align__(16) __nv_bfloat16 g_mih_l [GN_ * FD_];
__device__ __align__(16) __nv_bfloat16 g_mhh_h [GN_ * FD_];
__device__ __align__(16) __nv_bfloat16 g_mhh_l [GN_ * FD_];

__device__ __forceinline__ float lrelu_(float x) { return x > 0.f ? x : 0.01f * x; }
__device__ __forceinline__ float elu_(float x)   { return x > 0.f ? x : expm1f(x); }
__device__ __forceinline__ float sigm_(float x)  { return 1.f / (1.f + expf(-x)); }

__device__ __forceinline__ void split_bf16(float v, __nv_bfloat16* hp, __nv_bfloat16* lp) {
    __nv_bfloat16 h = __float2bfloat16(v);
    *hp = h;
    *lp = __float2bfloat16(v - __bfloat162float(h));
}

// ---------------------------------------------------------------------------
// mma.sync + ldmatrix helpers (baseline PTX, works on compute_103 target)
// ---------------------------------------------------------------------------
__device__ __forceinline__ uint32_t smem_u32_(const void* p) {
    uint32_t a;
    asm("{ .reg .u64 t; cvta.to.shared.u64 t, %1; cvt.u32.u64 %0, t; }" : "=r"(a) : "l"(p));
    return a;
}
__device__ __forceinline__ void ldm_x4_(uint32_t* r, uint32_t addr) {
    asm volatile("ldmatrix.sync.aligned.m8n8.x4.shared.b16 {%0,%1,%2,%3}, [%4];"
                 : "=r"(r[0]), "=r"(r[1]), "=r"(r[2]), "=r"(r[3]) : "r"(addr));
}
__device__ __forceinline__ void mma_(float* d, const uint32_t* a, uint32_t b0, uint32_t b1) {
    asm volatile(
        "mma.sync.aligned.m16n8k16.row.col.f32.bf16.bf16.f32 "
        "{%0,%1,%2,%3}, {%4,%5,%6,%7}, {%8,%9}, {%0,%1,%2,%3};"
        : "+f"(d[0]), "+f"(d[1]), "+f"(d[2]), "+f"(d[3])
        : "r"(a[0]), "r"(a[1]), "r"(a[2]), "r"(a[3]), "r"(b0), "r"(b1));
}

// ---------------------------------------------------------------------------
// Tensor-core GEMM (HMMA): C[M,N] = (Ahi+Alo)[M,256] @ (Whi+Wlo)[N,256]^T
// 3-product bf16 emulation (hh + hl + lh). CTA: 128 thr / 4 warps,
// tile 128x64 (warp tile 64x32). K staged in 4 chunks of 64, smem stride 72.
// EPI 0: Cf = acc + bias[n]  (fp32)
// EPI 2: elu(acc + rs[m]*bias[n]) -> Chi/Clo bf16 split
// gridDim.z==2 selects second (A2/W2/bias2/C2f) problem.
// ---------------------------------------------------------------------------
namespace {
constexpr int SMS_ = 72;                         // smem row stride (bf16)
constexpr int OFF_AH = 0;                        // bytes
constexpr int OFF_AL = 128 * SMS_ * 2;           // 18432
constexpr int OFF_WH = OFF_AL * 2;               // 36864
constexpr int OFF_WL = OFF_WH + 64 * SMS_ * 2;   // 46080
constexpr int SM_TOTAL = OFF_WL + 64 * SMS_ * 2; // 55296
}

template <int EPI>
__global__ __launch_bounds__(128)
void tgemm(const __nv_bfloat16* __restrict__ Ahi, const __nv_bfloat16* __restrict__ Alo,
           const __nv_bfloat16* __restrict__ A2hi, const __nv_bfloat16* __restrict__ A2lo,
           const __nv_bfloat16* __restrict__ Whi, const __nv_bfloat16* __restrict__ Wlo,
           const __nv_bfloat16* __restrict__ W2hi, const __nv_bfloat16* __restrict__ W2lo,
           const float* __restrict__ bias, const float* __restrict__ bias2,
           const float* __restrict__ rs,
           float* __restrict__ Cf, float* __restrict__ C2f,
           __nv_bfloat16* __restrict__ Chi, __nv_bfloat16* __restrict__ Clo,
           int N)
{
    extern __shared__ char sm[];
    const uint32_t smb = smem_u32_(sm);
    const int tid = threadIdx.x, wid = tid >> 5, lane = tid & 31;
    if (blockIdx.z) { Ahi = A2hi; Alo = A2lo; Whi = W2hi; Wlo = W2lo; bias = bias2; Cf = C2f; }
    const int bm = blockIdx.y * 128, bn = blockIdx.x * 64;
    constexpr int K = 256;
    const int warp_m = wid >> 1, warp_n = wid & 1;   // 2x2 warp grid

    float acc[4][4][4] = {};

    // per-lane ldmatrix address components
    const int lrow = lane & 15;                 // fragment row
    const int lcol = (lane >> 4) << 3;          // 0 or 8 (bf16 cols)

    for (int kc = 0; kc < 4; kc++) {
        const int koff = kc * 64;
        if (kc) __syncthreads();
        // stage A: 128 rows x 64 bf16, per value. 1024 uint4 per value.
        for (int i = tid; i < 1024; i += 128) {
            int r = i >> 3, c8 = (i & 7) << 3;
            uint32_t dst = (uint32_t)(r * SMS_ + c8) * 2;
            size_t g = (size_t)(bm + r) * K + koff + c8;
            *(uint4*)(sm + OFF_AH + dst) = *(const uint4*)(Ahi + g);
            *(uint4*)(sm + OFF_AL + dst) = *(const uint4*)(Alo + g);
        }
        // stage W: 64 rows x 64 bf16
        for (int i = tid; i < 512; i += 128) {
            int r = i >> 3, c8 = (i & 7) << 3;
            uint32_t dst = (uint32_t)(r * SMS_ + c8) * 2;
            size_t g = (size_t)(bn + r) * K + koff + c8;
            *(uint4*)(sm + OFF_WH + dst) = *(const uint4*)(Whi + g);
            *(uint4*)(sm + OFF_WL + dst) = *(const uint4*)(Wlo + g);
        }
        __syncthreads();

#pragma unroll
        for (int ks = 0; ks < 4; ks++) {
            const int k0 = ks * 16;
            uint32_t ah[4][4], al[4][4], bh[2][4], bl[2][4];
#pragma unroll
            for (int i = 0; i < 4; i++) {
                uint32_t off = (uint32_t)((warp_m * 64 + i * 16 + lrow) * SMS_ + k0 + lcol) * 2;
                ldm_x4_(ah[i], smb + OFF_AH + off);
                ldm_x4_(al[i], smb + OFF_AL + off);
            }
#pragma unroll
            for (int j2 = 0; j2 < 2; j2++) {
                uint32_t off = (uint32_t)((warp_n * 32 + j2 * 16 + lrow) * SMS_ + k0 + lcol) * 2;
                ldm_x4_(bh[j2], smb + OFF_WH + off);
                ldm_x4_(bl[j2], smb + OFF_WL + off);
            }
            // b frags: ntile j = j2*2 + s: b0 = r[s], b1 = r[s+2]
#pragma unroll
            for (int i = 0; i < 4; i++) {
#pragma unroll
                for (int j2 = 0; j2 < 2; j2++) {
#pragma unroll
                    for (int s = 0; s < 2; s++) {
                        float* d = acc[i][j2 * 2 + s];
                        mma_(d, ah[i], bh[j2][s], bh[j2][s + 2]);   // hi*hi
                        mma_(d, ah[i], bl[j2][s], bl[j2][s + 2]);   // hi*lo
                        mma_(d, al[i], bh[j2][s], bh[j2][s + 2]);   // lo*hi
                    }
                }
            }
        }
    }

    // epilogue: thread (lane) owns rows (t/4, t/4+8), cols 2*(t%4)..+1 per tile
    const int er = lane >> 2, ec = (lane & 3) << 1;
#pragma unroll
    for (int i = 0; i < 4; i++) {
        int m0 = bm + warp_m * 64 + i * 16 + er;
#pragma unroll
        for (int j = 0; j < 4; j++) {
            int n0 = bn + warp_n * 32 + j * 8 + ec;
            float b0 = bias[n0], b1 = bias[n0 + 1];
            if (EPI == 0) {
#pragma unroll
                for (int h = 0; h < 2; h++) {
                    int m = m0 + h * 8;
                    float2 o;
                    o.x = acc[i][j][2 * h + 0] + b0;
                    o.y = acc[i][j][2 * h + 1] + b1;
                    *(float2*)(Cf + (size_t)m * N + n0) = o;
                }
            } else {
#pragma unroll
                for (int h = 0; h < 2; h++) {
                    int m = m0 + h * 8;
                    float rsv = rs[m];
                    float v0 = elu_(acc[i][j][2 * h + 0] + rsv * b0);
                    float v1 = elu_(acc[i][j][2 * h + 1] + rsv * b1);
                    __nv_bfloat16 h0, l0, h1, l1;
                    split_bf16(v0, &h0, &l0); split_bf16(v1, &h1, &l1);
                    *(__nv_bfloat162*)(Chi + (size_t)m * N + n0) = __nv_bfloat162{h0, h1};
                    *(__nv_bfloat162*)(Clo + (size_t)m * N + n0) = __nv_bfloat162{l0, l1};
                }
            }
        }
    }
}

// ---------------------------------------------------------------------------
// fp32 -> bf16 hi/lo conversion (weights)
// ---------------------------------------------------------------------------
__global__ void fp_cvt(const float* __restrict__ x, __nv_bfloat16* __restrict__ hi,
                       __nv_bfloat16* __restrict__ lo, int n)
{
    int i = blockIdx.x * 256 + threadIdx.x;
    if (i >= n) return;
    split_bf16(x[i], hi + i, lo + i);
}

// ---------------------------------------------------------------------------
// atom_fc: lrelu(X @ W^T + b); writes fp32 + bf16 hi/lo
// ---------------------------------------------------------------------------
__global__ __launch_bounds__(256)
void fp_atom_fc(const float* __restrict__ X, const float* __restrict__ W,
                const float* __restrict__ bias, float* __restrict__ C,
                __nv_bfloat16* __restrict__ Ch, __nv_bfloat16* __restrict__ Cl)
{
    __shared__ float sin_[16][IN_ATOM_];
    const int r0 = blockIdx.x * 16;
    for (int i = threadIdx.x; i < 16 * IN_ATOM_; i += 256)
        sin_[i / IN_ATOM_][i % IN_ATOM_] =
            X[(size_t)(r0 + i / IN_ATOM_) * IN_ATOM_ + i % IN_ATOM_];
    __syncthreads();
    const int f = threadIdx.x;
    float acc[16] = {};
    for (int k = 0; k < IN_ATOM_; k++) {
        float wv = __ldg(&W[f * IN_ATOM_ + k]);
#pragma unroll
        for (int r = 0; r < 16; r++) acc[r] += wv * sin_[r][k];
    }
    float bv = bias[f];
#pragma unroll
    for (int r = 0; r < 16; r++) {
        float v = lrelu_(acc[r] + bv);
        size_t o = (size_t)(r0 + r) * FD_ + f;
        C[o] = v;
        split_bf16(v, Ch + o, Cl + o);
    }
}

// ---------------------------------------------------------------------------
// neighbor_fc
// ---------------------------------------------------------------------------
__global__ __launch_bounds__(256)
void fp_neighbor_fc(const float* __restrict__ atom_list, const float* __restrict__ bond_list,
                    const int* __restrict__ adeg, const int* __restrict__ bdeg,
                    const float* __restrict__ W, const float* __restrict__ bias,
                    float* __restrict__ C)
{
    constexpr int KIN = IN_ATOM_ + IN_BOND_;
    __shared__ float sin_[16][KIN];
    const int r0 = blockIdx.x * 16;
    for (int i = threadIdx.x; i < 16 * KIN; i += 256) {
        int r = i / KIN, k = i % KIN;
        int rid = r0 + r;
        int bb = rid / (L_ * D_);
        float v;
        if (k < IN_ATOM_) v = atom_list[((size_t)bb * L_ + adeg[rid]) * IN_ATOM_ + k];
        else              v = bond_list[((size_t)bb * NBONDS_ + bdeg[rid]) * IN_BOND_ + (k - IN_ATOM_)];
        sin_[r][k] = v;
    }
    __syncthreads();
    const int f = threadIdx.x;
    float acc[16] = {};
    for (int k = 0; k < KIN; k++) {
        float wv = __ldg(&W[f * KIN + k]);
#pragma unroll
        for (int r = 0; r < 16; r++) acc[r] += wv * sin_[r][k];
    }
    float bv = bias[f];
#pragma unroll
    for (int r = 0; r < 16; r++)
        C[(size_t)(r0 + r) * FD_ + f] = lrelu_(acc[r] + bv);
}

// ---------------------------------------------------------------------------
// Warp-per-row dots
// ---------------------------------------------------------------------------
__global__ void fp_rowdot(const float* __restrict__ X, const float* __restrict__ v,
                          float* __restrict__ y, int M)
{
    int warp = (blockIdx.x * blockDim.x + threadIdx.x) >> 5;
    int lane = threadIdx.x & 31;
    if (warp >= M) return;
    const float* x = X + (size_t)warp * FD_;
    float s = 0.f;
#pragma unroll
    for (int k = lane; k < FD_; k += 32) s += x[k] * v[k];
#pragma unroll
    for (int o = 16; o; o >>= 1) s += __shfl_down_sync(0xffffffffu, s, o);
    if (lane == 0) y[warp] = s;
}

__global__ void fp_rowdot2(const float* __restrict__ X, const float* __restrict__ v1,
                           const float* __restrict__ v2,
                           float* __restrict__ y1, float* __restrict__ y2, int M)
{
    int warp = (blockIdx.x * blockDim.x + threadIdx.x) >> 5;
    int lane = threadIdx.x & 31;
    if (warp >= M) return;
    const float* x = X + (size_t)warp * FD_;
    float s1 = 0.f, s2 = 0.f;
#pragma unroll
    for (int k = lane; k < FD_; k += 32) {
        float xv = x[k];
        s1 += xv * v1[k];
        s2 += xv * v2[k];
    }
#pragma unroll
    for (int o = 16; o; o >>= 1) {
        s1 += __shfl_down_sync(0xffffffffu, s1, o);
        s2 += __shfl_down_sync(0xffffffffu, s2, o);
    }
    if (lane == 0) { y1[warp] = s1; y2[warp] = s2; }
}

__global__ void fp_actdot4(const float* __restrict__ X, const float* __restrict__ maw,
                           float* __restrict__ y)
{
    int warp = (blockIdx.x * blockDim.x + threadIdx.x) >> 5;
    int lane = threadIdx.x & 31;
    if (warp >= BL_) return;
    const float* x = X + (size_t)warp * FD_;
    float s0 = 0.f, s1 = 0.f, s2 = 0.f, s3 = 0.f;
#pragma unroll
    for (int k = lane; k < FD_; k += 32) {
        float xv = x[k];
        s0 += xv * maw[0 * 512 + 256 + k];
        s1 += xv * maw[1 * 512 + 256 + k];
        s2 += xv * maw[2 * 512 + 256 + k];
        s3 += xv * maw[3 * 512 + 256 + k];
    }
#pragma unroll
    for (int o = 16; o; o >>= 1) {
        s0 += __shfl_down_sync(0xffffffffu, s0, o);
        s1 += __shfl_down_sync(0xffffffffu, s1, o);
        s2 += __shfl_down_sync(0xffffffffu, s2, o);
        s3 += __shfl_down_sync(0xffffffffu, s3, o);
    }
    if (lane == 0) {
        y[0 * BL_ + warp] = s0; y[1 * BL_ + warp] = s1;
        y[2 * BL_ + warp] = s2; y[3 * BL_ + warp] = s3;
    }
}

// ---------------------------------------------------------------------------
// scores + softmax over D=6
// ---------------------------------------------------------------------------
template <int FIRST>
__global__ void fp_score(const float* __restrict__ sd, const float* __restrict__ nd,
                         const int* __restrict__ adeg, const float* __restrict__ ab_ptr,
                         float* __restrict__ w, float* __restrict__ wsum)
{
    int m = blockIdx.x * blockDim.x + threadIdx.x;
    if (m >= BL_) return;
    int b = m / L_;
    float ab = ab_ptr[0];
    float sdv = sd[m];
    float sc[D_], msk[D_];
    float mx = -3.4e38f;
#pragma unroll
    for (int d = 0; d < D_; d++) {
        int idx = adeg[m * D_ + d];
        float ndv = FIRST ? nd[m * D_ + d] : nd[b * L_ + idx];
        float s = lrelu_(sdv + ndv + ab);
        bool pad = (idx == L_ - 1);
        if (pad) s += NEG_;
        msk[d] = pad ? 0.f : 1.f;
        sc[d] = s;
        mx = fmaxf(mx, s);
    }
    float sum = 0.f;
#pragma unroll
    for (int d = 0; d < D_; d++) { float e = expf(sc[d] - mx); sum += e; sc[d] = e; }
    float inv = 1.f / sum, ws = 0.f;
#pragma unroll
    for (int d = 0; d < D_; d++) {
        float wv = sc[d] * inv * msk[d];
        w[m * D_ + d] = wv;
        ws += wv;
    }
    wsum[m] = ws;
}

// ---------------------------------------------------------------------------
// weighted neighbor sum -> bf16 hi/lo out
// ---------------------------------------------------------------------------
template <int FIRST>
__global__ __launch_bounds__(256)
void fp_wf(const float* __restrict__ w, const int* __restrict__ adeg,
           const float* __restrict__ src, __nv_bfloat16* __restrict__ wfh,
           __nv_bfloat16* __restrict__ wfl)
{
    __shared__ float sw[2][D_];
    __shared__ int sidx[2][D_];
    const int m0 = blockIdx.x * 2;
    if (threadIdx.x < 2 * D_) {
        int r = threadIdx.x / D_, d = threadIdx.x % D_;
        sw[r][d] = w[(m0 + r) * D_ + d];
        sidx[r][d] = adeg[(m0 + r) * D_ + d];
    }
    __syncthreads();
    const int f = threadIdx.x;
#pragma unroll
    for (int r = 0; r < 2; r++) {
        int m = m0 + r;
        int b = m / L_;
        float acc = 0.f;
#pragma unroll
        for (int d = 0; d < D_; d++) {
            float xv = FIRST ? src[((size_t)m * D_ + d) * FD_ + f]
                             : src[(size_t)(b * L_ + sidx[r][d]) * FD_ + f];
            acc += sw[r][d] * xv;
        }
        split_bf16(acc, wfh + (size_t)m * FD_ + f, wfl + (size_t)m * FD_ + f);
    }
}

// ---------------------------------------------------------------------------
// GRU gate fuse with optional bf16 splits and outputs
// ---------------------------------------------------------------------------
__global__ void fp_gru_gate(const float* __restrict__ gi, const float* __restrict__ gh,
                            const float* __restrict__ hin, float* __restrict__ hout,
                            __nv_bfloat16* __restrict__ hh, __nv_bfloat16* __restrict__ hl,
                            float* __restrict__ act,
                            __nv_bfloat16* __restrict__ ah, __nv_bfloat16* __restrict__ al,
                            float* __restrict__ out, int M)
{
    int g = blockIdx.x * blockDim.x + threadIdx.x;
    if (g >= M * FD_) return;
    int m = g / FD_, f = g - m * FD_;
    const float* gim = gi + (size_t)m * GN_;
    const float* ghm = gh + (size_t)m * GN_;
    float r = sigm_(gim[f] + ghm[f]);
    float z = sigm_(gim[FD_ + f] + ghm[FD_ + f]);
    float n = tanhf(gim[2 * FD_ + f] + r * ghm[2 * FD_ + f]);
    float h = (1.f - z) * n + z * hin[g];
    hout[g] = h;
    if (hh) split_bf16(h, hh + g, hl + g);
    float a = fmaxf(h, 0.f);
    if (act) act[g] = a;
    if (ah) split_bf16(a, ah + g, al + g);
    if (out) out[g] = a;
}

// ---------------------------------------------------------------------------
// molecule feature init
// ---------------------------------------------------------------------------
__global__ void fp_molfeat(const float* __restrict__ act, const float* __restrict__ amask,
                           float* __restrict__ mf, __nv_bfloat16* __restrict__ mfh,
                           __nv_bfloat16* __restrict__ mfl, float* __restrict__ am)
{
    int b = blockIdx.x, f = threadIdx.x;
    float acc = 0.f;
    for (int l = 0; l < L_; l++)
        acc += act[((size_t)b * L_ + l) * FD_ + f] * amask[b * L_ + l];
    mf[b * FD_ + f] = acc;
    split_bf16(acc, mfh + b * FD_ + f, mfl + b * FD_ + f);
    am[b * FD_ + f] = fmaxf(acc, 0.f);
}

// ---------------------------------------------------------------------------
// Fused mol score + softmax + context (per molecule block)
// ---------------------------------------------------------------------------
__global__ __launch_bounds__(128)
void fp_molstep(const float* __restrict__ actmol, const float* __restrict__ maw,
                const float* __restrict__ mab, const float* __restrict__ actdot,
                const float* __restrict__ amask, const float* __restrict__ actT,
                __nv_bfloat16* __restrict__ ctxh, __nv_bfloat16* __restrict__ ctxl, int task)
{
    __shared__ float red[128];
    __shared__ float sw[128];
    int b = blockIdx.x, t = threadIdx.x;
    const float* ms = maw + task * 2 * FD_;
    float p = actmol[b * FD_ + t] * ms[t] + actmol[b * FD_ + 128 + t] * ms[128 + t];
    red[t] = p; __syncthreads();
    for (int st = 64; st; st >>= 1) { if (t < st) red[t] += red[t + st]; __syncthreads(); }
    float sdv = red[0]; __syncthreads();
    float amv = amask[b * L_ + t];
    float s = lrelu_(sdv + actdot[task * BL_ + b * L_ + t] + mab[task]);
    if (amv == 0.f) s += NEG_;
    red[t] = s; __syncthreads();
    for (int st = 64; st; st >>= 1) { if (t < st) red[t] = fmaxf(red[t], red[t + st]); __syncthreads(); }
    float mx = red[0]; __syncthreads();
    float e = expf(s - mx);
    red[t] = e; __syncthreads();
    for (int st = 64; st; st >>= 1) { if (t < st) red[t] += red[t + st]; __syncthreads(); }
    float sum = red[0];
    sw[t] = e / sum * amv;
    __syncthreads();
    float a0 = 0.f, a1 = 0.f;
    for (int l = 0; l < L_; l++) {
        float wv = sw[l];
        const float* row = actT + ((size_t)b * L_ + l) * FD_;
        a0 += wv * row[t];
        a1 += wv * row[t + 128];
    }
    a0 = elu_(a0); a1 = elu_(a1);
    split_bf16(a0, ctxh + b * FD_ + t, ctxl + b * FD_ + t);
    split_bf16(a1, ctxh + b * FD_ + 128 + t, ctxl + b * FD_ + 128 + t);
}

// ---------------------------------------------------------------------------
// Host launch sequence
// ---------------------------------------------------------------------------
extern "C" void kernel_launch(void* const* d_in, const int* in_sizes, int n_in,
                              void* d_out, int out_size)
{
    const float* atom_list = (const float*)d_in[0];
    const float* bond_list = (const float*)d_in[1];
    const int*   adeg      = (const int*)d_in[2];
    const int*   bdeg      = (const int*)d_in[3];
    const float* amask     = (const float*)d_in[4];
    const float* atom_fc_w = (const float*)d_in[5];
    const float* atom_fc_b = (const float*)d_in[6];
    const float* nbr_fc_w  = (const float*)d_in[7];
    const float* nbr_fc_b  = (const float*)d_in[8];
    const float* align_w   = (const float*)d_in[9];
    const float* align_b   = (const float*)d_in[10];
    const float* attend_w  = (const float*)d_in[11];
    const float* attend_b  = (const float*)d_in[12];
    const float* gru_wih   = (const float*)d_in[13];
    const float* gru_whh   = (const float*)d_in[14];
    const float* gru_bih   = (const float*)d_in[15];
    const float* gru_bhh   = (const float*)d_in[16];
    const float* mgru_wih  = (const float*)d_in[17];
    const float* mgru_whh  = (const float*)d_in[18];
    const float* mgru_bih  = (const float*)d_in[19];
    const float* mgru_bhh  = (const float*)d_in[20];
    const float* mal_w     = (const float*)d_in[21];
    const float* mal_b     = (const float*)d_in[22];
    const float* mat_w     = (const float*)d_in[23];
    const float* mat_b     = (const float*)d_in[24];
    float* out = (float*)d_out;

    cudaFuncSetAttribute((const void*)tgemm<0>, cudaFuncAttributeMaxDynamicSharedMemorySize, SM_TOTAL);
    cudaFuncSetAttribute((const void*)tgemm<2>, cudaFuncAttributeMaxDynamicSharedMemorySize, SM_TOTAL);

#define SYM(p, s) cudaGetSymbolAddress((void**)&p, s)
    float *p_af, *p_nbr, *p_h, *p_act, *p_actT, *p_gi, *p_gh, *p_nd0, *p_sd, *p_nd,
          *p_w, *p_ws, *p_ad, *p_mf, *p_am, *p_mgi, *p_mgh;
    __nv_bfloat16 *p_afh, *p_afl, *p_wfh, *p_wfl, *p_cxh, *p_cxl, *p_hh, *p_hl,
                  *p_ach, *p_acl, *p_mch, *p_mcl, *p_mfh, *p_mfl,
                  *w_atth, *w_attl, *w_ihh, *w_ihl, *w_hhh, *w_hhl,
                  *w_math, *w_matl, *w_mihh, *w_mihl, *w_mhhh, *w_mhhl;
    SYM(p_af, g_atomfeat); SYM(p_nbr, g_nbrfeat); SYM(p_h, g_h); SYM(p_act, g_act);
    SYM(p_actT, g_actT); SYM(p_gi, g_gi); SYM(p_gh, g_gh); SYM(p_nd0, g_nbrdot0);
    SYM(p_sd, g_sd); SYM(p_nd, g_nd); SYM(p_w, g_w); SYM(p_ws, g_wsum);
    SYM(p_ad, g_actdot); SYM(p_mf, g_molfeat); SYM(p_am, g_actmol);
    SYM(p_mgi, g_mgi); SYM(p_mgh, g_mgh);
    SYM(p_afh, g_af_h); SYM(p_afl, g_af_l); SYM(p_wfh, g_wf_h); SYM(p_wfl, g_wf_l);
    SYM(p_cxh, g_ctx_h); SYM(p_cxl, g_ctx_l); SYM(p_hh, g_h_h); SYM(p_hl, g_h_l);
    SYM(p_ach, g_act_h); SYM(p_acl, g_act_l); SYM(p_mch, g_mctx_h); SYM(p_mcl, g_mctx_l);
    SYM(p_mfh, g_mf_h); SYM(p_mfl, g_mf_l);
    SYM(w_atth, g_watt_h); SYM(w_attl, g_watt_l); SYM(w_ihh, g_wih_h); SYM(w_ihl, g_wih_l);
    SYM(w_hhh, g_whh_h); SYM(w_hhl, g_whh_l); SYM(w_math, g_mat_h); SYM(w_matl, g_mat_l);
    SYM(w_mihh, g_mih_h); SYM(w_mihl, g_mih_l); SYM(w_mhhh, g_mhh_h); SYM(w_mhhl, g_mhh_l);
#undef SYM

    // --- weight conversions ---
    fp_cvt<<<(RADIUS_ * FD_ * FD_) / 256, 256>>>(attend_w, w_atth, w_attl, RADIUS_ * FD_ * FD_);
    fp_cvt<<<(RADIUS_ * GN_ * FD_) / 256, 256>>>(gru_wih, w_ihh, w_ihl, RADIUS_ * GN_ * FD_);
    fp_cvt<<<(RADIUS_ * GN_ * FD_) / 256, 256>>>(gru_whh, w_hhh, w_hhl, RADIUS_ * GN_ * FD_);
    fp_cvt<<<(FD_ * FD_) / 256, 256>>>(mat_w, w_math, w_matl, FD_ * FD_);
    fp_cvt<<<(GN_ * FD_) / 256, 256>>>(mgru_wih, w_mihh, w_mihl, GN_ * FD_);
    fp_cvt<<<(GN_ * FD_) / 256, 256>>>(mgru_whh, w_mhhh, w_mhhl, GN_ * FD_);

    fp_atom_fc<<<BL_ / 16, 256>>>(atom_list, atom_fc_w, atom_fc_b, p_af, p_afh, p_afl);
    fp_neighbor_fc<<<BLD_ / 16, 256>>>(atom_list, bond_list, adeg, bdeg, nbr_fc_w, nbr_fc_b, p_nbr);

    const dim3 gctx(FD_ / 64, BL_ / 128, 1);      // 16384 x 256
    const dim3 ggru(GN_ / 64, BL_ / 128, 2);      // 16384 x 768, batched gi/gh
    const dim3 gmol(GN_ / 64, B_ / 128, 2);       // 128 x 768, batched gi/gh

    // --- radius loop ---
    for (int r = 0; r < RADIUS_; r++) {
        const __nv_bfloat16* hprev_h = (r == 0) ? p_afh : p_hh;
        const __nv_bfloat16* hprev_l = (r == 0) ? p_afl : p_hl;
        const float* hprev_f = (r == 0) ? p_af : p_h;

        if (r == 0) {
            fp_rowdot<<<BLD_ / 8, 256>>>(p_nbr, align_w + 256, p_nd0, BLD_);
            fp_rowdot<<<BL_ / 8, 256>>>(p_af, align_w, p_sd, BL_);
            fp_score<1><<<BL_ / 256, 256>>>(p_sd, p_nd0, adeg, align_b, p_w, p_ws);
            fp_wf<1><<<BL_ / 2, 256>>>(p_w, adeg, p_nbr, p_wfh, p_wfl);
        } else {
            fp_rowdot2<<<BL_ / 8, 256>>>(p_act, align_w + r * 512, align_w + r * 512 + 256,
                                         p_sd, p_nd, BL_);
            fp_score<0><<<BL_ / 256, 256>>>(p_sd, p_nd, adeg, align_b + r, p_w, p_ws);
            fp_wf<0><<<BL_ / 2, 256>>>(p_w, adeg, p_act, p_wfh, p_wfl);
        }
        // ctx = elu(wf @ attend^T + wsum*b) -> bf16 split
        tgemm<2><<<gctx, 128, SM_TOTAL>>>(p_wfh, p_wfl, nullptr, nullptr,
                                          w_atth + (size_t)r * FD_ * FD_, w_attl + (size_t)r * FD_ * FD_,
                                          nullptr, nullptr,
                                          attend_b + r * FD_, nullptr, p_ws,
                                          nullptr, nullptr, p_cxh, p_cxl, FD_);
        // gi = ctx @ wih^T + bih ; gh = hprev @ whh^T + bhh   (batched)
        tgemm<0><<<ggru, 128, SM_TOTAL>>>(p_cxh, p_cxl, hprev_h, hprev_l,
                                          w_ihh + (size_t)r * GN_ * FD_, w_ihl + (size_t)r * GN_ * FD_,
                                          w_hhh + (size_t)r * GN_ * FD_, w_hhl + (size_t)r * GN_ * FD_,
                                          gru_bih + r * GN_, gru_bhh + r * GN_, nullptr,
                                          p_gi, p_gh, nullptr, nullptr, GN_);
        bool last = (r == RADIUS_ - 1);
        fp_gru_gate<<<BL_ * FD_ / 256, 256>>>(p_gi, p_gh, hprev_f, p_h, p_hh, p_hl,
                                              p_act, last ? p_ach : nullptr, last ? p_acl : nullptr,
                                              nullptr, BL_);
    }

    // --- molecule phase ---
    fp_molfeat<<<B_, FD_>>>(p_act, amask, p_mf, p_mfh, p_mfl, p_am);
    tgemm<0><<<gctx, 128, SM_TOTAL>>>(p_ach, p_acl, nullptr, nullptr,
                                      w_math, w_matl, nullptr, nullptr,
                                      mat_b, nullptr, nullptr,
                                      p_actT, nullptr, nullptr, nullptr, FD_);
    fp_actdot4<<<BL_ / 8, 256>>>(p_act, mal_w, p_ad);

    for (int i = 0; i < TASKS_; i++) {
        for (int t = 0; t < T_; t++) {
            fp_molstep<<<B_, 128>>>(p_am, mal_w, mal_b, p_ad, amask, p_actT, p_mch, p_mcl, i);
            tgemm<0><<<gmol, 128, SM_TOTAL>>>(p_mch, p_mcl, p_mfh, p_mfl,
                                              w_mihh, w_mihl, w_mhhh, w_mhhl,
                                              mgru_bih, mgru_bhh, nullptr,
                                              p_mgi, p_mgh, nullptr, nullptr, GN_);
            fp_gru_gate<<<B_ * FD_ / 256, 256>>>(p_mgi, p_mgh, p_mf, p_mf, p_mfh, p_mfl,
                                                 p_am, nullptr, nullptr,
                                                 (t == T_ - 1) ? out + (size_t)i * B_ * FD_ : nullptr,
                                                 B_);
        }
    }
}